// round 10
// baseline (speedup 1.0000x reference)
#include <cuda_runtime.h>
#include <cuda_fp16.h>
#include <cstdint>

// InstantNGP hash embedding. Only levels 0..7 contribute to out[:, :16].
// Resolutions R: 16,20,25,32,40,50,64,80.
//
//   stage A (fused): per 8x8x8-cell tile, hash-gather the 9^3 corner lattice
//            into smem, pack 512 cells. Cell = 32B, FEATURE-SPLIT:
//            [feat0 of 8 corners, fp16*2^13][feat1 of 8 corners].
//   stage B: paired-lane trilinear interp, BATCHED: per pass, levels are
//            processed in 2 batches of 4 with explicit u[4] arrays so 4
//            LDG.128 are in flight per thread (MLP 4) before consumption.

#define N_POINTS   1048576
#define LOG2_T     19
#define TABLE_SIZE (1u << LOG2_T)
#define TABLE_MASK (TABLE_SIZE - 1u)
#define NLV 8

#define P1 2654435761u
#define P2 805459861u

#define FSCALE     8192.0f          // 2^13 exact
#define INV_FSCALE 1.220703125e-4f  // 2^-13 exact

// cells per axis D=R+1 (floor can reach R at x==1)
#define TOTAL_CELLS 1075325

__device__ uint4 g_cube[(size_t)TOTAL_CELLS * 2];   // 32B per cell

__constant__ int c_R[NLV]       = {16, 20, 25, 32, 40, 50, 64, 80};
__constant__ int c_cellOff[NLV] = {0, 4913, 14174, 31750, 67687, 136608, 269259, 543884};
// tiles per axis = ceil((R+1)/8); cumulative tile counts
__constant__ int c_TD[NLV]      = {3, 3, 4, 5, 6, 7, 9, 11};
__constant__ int c_tileOff[NLV] = {0, 27, 54, 118, 243, 459, 802, 1531};
#define TOTAL_TILES 2862

// ---- stage A: fused gather + feature-split cell assembly ------------------
__global__ __launch_bounds__(256) void build_cube_fused(const float* __restrict__ tables)
{
    __shared__ float2 sc[9 * 9 * 9];   // 5832B corner lattice

    int b = blockIdx.x;
    int lvl = 0;
    #pragma unroll
    for (int l = 1; l < NLV; ++l)
        if (b >= c_tileOff[l]) lvl = l;
    b -= c_tileOff[lvl];

    const int TD = c_TD[lvl];
    const int tz = b % TD;
    const int tt = b / TD;
    const int ty = tt % TD;
    const int tx = tt / TD;

    const int R = c_R[lvl];
    const int D = R + 1;
    const int tid = threadIdx.x;

    const float2* __restrict__ T =
        (const float2*)(tables + (size_t)lvl * TABLE_SIZE * 2);

    for (int idx = tid; idx < 729; idx += 256) {
        const int jz = idx % 9;
        const int jt = idx / 9;
        const int jy = jt % 9;
        const int jx = jt / 9;
        const uint32_t gx = (uint32_t)(tx * 8 + jx);
        const uint32_t gy = (uint32_t)(ty * 8 + jy);
        const uint32_t gz = (uint32_t)(tz * 8 + jz);
        const uint32_t h = (gx ^ (gy * P1) ^ (gz * P2)) & TABLE_MASK;
        sc[idx] = __ldg(T + h);
    }
    __syncthreads();

    for (int c = tid; c < 512; c += 256) {
        const int iz = c & 7;
        const int iy = (c >> 3) & 7;
        const int ix = c >> 6;
        const int bx = tx * 8 + ix;
        const int by = ty * 8 + iy;
        const int bz = tz * 8 + iz;
        if (bx >= D || by >= D || bz >= D) continue;

        const int s = (ix * 9 + iy) * 9 + iz;
        const float2 e000 = sc[s];
        const float2 e001 = sc[s + 1];
        const float2 e010 = sc[s + 9];
        const float2 e011 = sc[s + 10];
        const float2 e100 = sc[s + 81];
        const float2 e101 = sc[s + 82];
        const float2 e110 = sc[s + 90];
        const float2 e111 = sc[s + 91];

        // feature-split pack: u0 = feat0 (x), u1 = feat1 (y)
        // half2 pairs are (dz=0, dz=1) for each (dx,dy)
        #define PKH(a, bq) __float22half2_rn(make_float2((a) * FSCALE, (bq) * FSCALE))
        __half2 a0 = PKH(e000.x, e001.x), a1 = PKH(e010.x, e011.x);
        __half2 a2 = PKH(e100.x, e101.x), a3 = PKH(e110.x, e111.x);
        __half2 b0 = PKH(e000.y, e001.y), b1 = PKH(e010.y, e011.y);
        __half2 b2 = PKH(e100.y, e101.y), b3 = PKH(e110.y, e111.y);
        #undef PKH

        const int cell = (bx * D + by) * D + bz;
        uint4* dst = g_cube + ((size_t)c_cellOff[lvl] + cell) * 2;
        dst[0] = make_uint4(*(uint32_t*)&a0, *(uint32_t*)&a1,
                            *(uint32_t*)&a2, *(uint32_t*)&a3);
        dst[1] = make_uint4(*(uint32_t*)&b0, *(uint32_t*)&b1,
                            *(uint32_t*)&b2, *(uint32_t*)&b3);
    }
}

// ---- stage B: paired-lane (per-feature) trilinear interp, batched ---------
// N_POINTS is an exact multiple of 256: all warps full (shfl-safe).
__global__ __launch_bounds__(256) void hash_embed_kernel(
    const float* __restrict__ x,
    float* __restrict__ out)
{
    const int i    = blockIdx.x * blockDim.x + threadIdx.x;
    const int lane = threadIdx.x & 31;
    const unsigned FULL = 0xffffffffu;

    const float px = __ldg(x + 3 * (size_t)i + 0);
    const float py = __ldg(x + 3 * (size_t)i + 1);
    const float pz = __ldg(x + 3 * (size_t)i + 2);

    const float RES[NLV] = {16.f, 20.f, 25.f, 32.f, 40.f, 50.f, 64.f, 80.f};
    const int   IR[NLV]  = {16, 20, 25, 32, 40, 50, 64, 80};
    const int   OFF[NLV] = {0, 4913, 14174, 31750, 67687, 136608, 269259, 543884};

    const int feat  = lane & 1;           // which 16B feature block this lane fetches
    const int rsrc0 = (lane << 1) & 31;   // route-back: feat0 lane (feat1 = rsrc0|1)

    float o[16];

    #pragma unroll
    for (int t = 0; t < 2; ++t) {
        const int j = (t << 4) + (lane >> 1);   // point served by this lane pair

        const float pxj = __shfl_sync(FULL, px, j);
        const float pyj = __shfl_sync(FULL, py, j);
        const float pzj = __shfl_sync(FULL, pz, j);

        const float cxj = fminf(fmaxf(pxj, 0.0f), 1.0f);
        const float cyj = fminf(fmaxf(pyj, 0.0f), 1.0f);
        const float czj = fminf(fmaxf(pzj, 0.0f), 1.0f);

        #pragma unroll
        for (int hb = 0; hb < 2; ++hb) {
            uint4 u[4];
            float wxa[4], wya[4], wza[4];

            // load phase: 4 independent LDG.128 in flight
            #pragma unroll
            for (int k = 0; k < 4; ++k) {
                const int l = hb * 4 + k;
                const float R = RES[l];

                const float fbx = floorf(cxj * R);
                const float fby = floorf(cyj * R);
                const float fbz = floorf(czj * R);
                wxa[k] = fmaf(pxj, R, -fbx);
                wya[k] = fmaf(pyj, R, -fby);
                wza[k] = fmaf(pzj, R, -fbz);

                const int D    = IR[l] + 1;
                const int cell = ((int)fbx * D + (int)fby) * D + (int)fbz;
                u[k] = __ldg(g_cube + ((size_t)OFF[l] + cell) * 2 + feat);
            }

            // consume phase
            #pragma unroll
            for (int k = 0; k < 4; ++k) {
                const int l = hb * 4 + k;
                const float wx = wxa[k], wy = wya[k], wz = wza[k];

                // half2 pairs: (dz=0, dz=1) for (dx,dy) = 00,01,10,11
                const float2 v00 = __half22float2(*(const __half2*)&u[k].x);
                const float2 v01 = __half22float2(*(const __half2*)&u[k].y);
                const float2 v10 = __half22float2(*(const __half2*)&u[k].z);
                const float2 v11 = __half22float2(*(const __half2*)&u[k].w);

                const float iwz = 1.0f - wz;
                const float iwy = 1.0f - wy;

                const float z00 = v00.x * iwz + v00.y * wz;   // x=0,y=0
                const float z01 = v01.x * iwz + v01.y * wz;   // x=0,y=1
                const float z10 = v10.x * iwz + v10.y * wz;   // x=1,y=0
                const float z11 = v11.x * iwz + v11.y * wz;   // x=1,y=1

                const float y0 = z00 * iwy + z01 * wy;
                const float y1 = z10 * iwy + z11 * wy;
                const float res = y0 * (1.0f - wx) + y1 * wx;

                // route both features to the owning lane
                const float qa = __shfl_sync(FULL, res, rsrc0);
                const float qb = __shfl_sync(FULL, res, rsrc0 | 1);
                if ((lane >> 4) == t) {
                    o[2 * l + 0] = qa * INV_FSCALE;
                    o[2 * l + 1] = qb * INV_FSCALE;
                }
            }
        }
    }

    float4* __restrict__ o4 = (float4*)(out + (size_t)i * 16);
    o4[0] = make_float4(o[0],  o[1],  o[2],  o[3]);
    o4[1] = make_float4(o[4],  o[5],  o[6],  o[7]);
    o4[2] = make_float4(o[8],  o[9],  o[10], o[11]);
    o4[3] = make_float4(o[12], o[13], o[14], o[15]);
}

extern "C" void kernel_launch(void* const* d_in, const int* in_sizes, int n_in,
                              void* d_out, int out_size)
{
    const float* x      = (const float*)d_in[0];   // (N_POINTS, 3) f32
    const float* tables = (const float*)d_in[1];   // (16, TABLE_SIZE, 2) f32
    float* out          = (float*)d_out;           // (N_POINTS, 16) f32

    build_cube_fused<<<TOTAL_TILES, 256>>>(tables);
    hash_embed_kernel<<<N_POINTS / 256, 256>>>(x, out);
}

// round 11
// speedup vs baseline: 1.0355x; 1.0355x over previous
#include <cuda_runtime.h>
#include <cuda_fp16.h>
#include <cstdint>

// InstantNGP hash embedding. Only levels 0..7 contribute to out[:, :16].
// Resolutions R: 16,20,25,32,40,50,64,80.
//
//   stage A (fused): per 8x8x8-cell tile, hash-gather the 9^3 corner lattice
//            into smem, pack 512 cells. Cell = 32B, FEATURE-SPLIT:
//            [feat0 of 8 corners, fp16*2^13][feat1 of 8 corners].
//   stage B: paired-lane trilinear interp (round-9 form) with
//            __launch_bounds__(256, 6): cap regs at 42 -> 48 warps/SM.

#define N_POINTS   1048576
#define LOG2_T     19
#define TABLE_SIZE (1u << LOG2_T)
#define TABLE_MASK (TABLE_SIZE - 1u)
#define NLV 8

#define P1 2654435761u
#define P2 805459861u

#define FSCALE     8192.0f          // 2^13 exact
#define INV_FSCALE 1.220703125e-4f  // 2^-13 exact

// cells per axis D=R+1 (floor can reach R at x==1)
#define TOTAL_CELLS 1075325

__device__ uint4 g_cube[(size_t)TOTAL_CELLS * 2];   // 32B per cell

__constant__ int c_R[NLV]       = {16, 20, 25, 32, 40, 50, 64, 80};
__constant__ int c_cellOff[NLV] = {0, 4913, 14174, 31750, 67687, 136608, 269259, 543884};
// tiles per axis = ceil((R+1)/8); cumulative tile counts
__constant__ int c_TD[NLV]      = {3, 3, 4, 5, 6, 7, 9, 11};
__constant__ int c_tileOff[NLV] = {0, 27, 54, 118, 243, 459, 802, 1531};
#define TOTAL_TILES 2862

// ---- stage A: fused gather + feature-split cell assembly ------------------
__global__ __launch_bounds__(256) void build_cube_fused(const float* __restrict__ tables)
{
    __shared__ float2 sc[9 * 9 * 9];   // 5832B corner lattice

    int b = blockIdx.x;
    int lvl = 0;
    #pragma unroll
    for (int l = 1; l < NLV; ++l)
        if (b >= c_tileOff[l]) lvl = l;
    b -= c_tileOff[lvl];

    const int TD = c_TD[lvl];
    const int tz = b % TD;
    const int tt = b / TD;
    const int ty = tt % TD;
    const int tx = tt / TD;

    const int R = c_R[lvl];
    const int D = R + 1;
    const int tid = threadIdx.x;

    const float2* __restrict__ T =
        (const float2*)(tables + (size_t)lvl * TABLE_SIZE * 2);

    for (int idx = tid; idx < 729; idx += 256) {
        const int jz = idx % 9;
        const int jt = idx / 9;
        const int jy = jt % 9;
        const int jx = jt / 9;
        const uint32_t gx = (uint32_t)(tx * 8 + jx);
        const uint32_t gy = (uint32_t)(ty * 8 + jy);
        const uint32_t gz = (uint32_t)(tz * 8 + jz);
        const uint32_t h = (gx ^ (gy * P1) ^ (gz * P2)) & TABLE_MASK;
        sc[idx] = __ldg(T + h);
    }
    __syncthreads();

    for (int c = tid; c < 512; c += 256) {
        const int iz = c & 7;
        const int iy = (c >> 3) & 7;
        const int ix = c >> 6;
        const int bx = tx * 8 + ix;
        const int by = ty * 8 + iy;
        const int bz = tz * 8 + iz;
        if (bx >= D || by >= D || bz >= D) continue;

        const int s = (ix * 9 + iy) * 9 + iz;
        const float2 e000 = sc[s];
        const float2 e001 = sc[s + 1];
        const float2 e010 = sc[s + 9];
        const float2 e011 = sc[s + 10];
        const float2 e100 = sc[s + 81];
        const float2 e101 = sc[s + 82];
        const float2 e110 = sc[s + 90];
        const float2 e111 = sc[s + 91];

        // feature-split pack: u0 = feat0 (x), u1 = feat1 (y)
        // half2 pairs are (dz=0, dz=1) for each (dx,dy)
        #define PKH(a, bq) __float22half2_rn(make_float2((a) * FSCALE, (bq) * FSCALE))
        __half2 a0 = PKH(e000.x, e001.x), a1 = PKH(e010.x, e011.x);
        __half2 a2 = PKH(e100.x, e101.x), a3 = PKH(e110.x, e111.x);
        __half2 b0 = PKH(e000.y, e001.y), b1 = PKH(e010.y, e011.y);
        __half2 b2 = PKH(e100.y, e101.y), b3 = PKH(e110.y, e111.y);
        #undef PKH

        const int cell = (bx * D + by) * D + bz;
        uint4* dst = g_cube + ((size_t)c_cellOff[lvl] + cell) * 2;
        dst[0] = make_uint4(*(uint32_t*)&a0, *(uint32_t*)&a1,
                            *(uint32_t*)&a2, *(uint32_t*)&a3);
        dst[1] = make_uint4(*(uint32_t*)&b0, *(uint32_t*)&b1,
                            *(uint32_t*)&b2, *(uint32_t*)&b3);
    }
}

// ---- stage B: paired-lane (per-feature) trilinear interp -------------------
// N_POINTS is an exact multiple of 256: all warps full (shfl-safe).
// __launch_bounds__(256, 6): force regs <= 42 so 6 CTAs (48 warps) fit per SM.
__global__ __launch_bounds__(256, 6) void hash_embed_kernel(
    const float* __restrict__ x,
    float* __restrict__ out)
{
    const int i    = blockIdx.x * blockDim.x + threadIdx.x;
    const int lane = threadIdx.x & 31;
    const unsigned FULL = 0xffffffffu;

    const float px = __ldg(x + 3 * (size_t)i + 0);
    const float py = __ldg(x + 3 * (size_t)i + 1);
    const float pz = __ldg(x + 3 * (size_t)i + 2);

    const float RES[NLV] = {16.f, 20.f, 25.f, 32.f, 40.f, 50.f, 64.f, 80.f};
    const int   IR[NLV]  = {16, 20, 25, 32, 40, 50, 64, 80};
    const int   OFF[NLV] = {0, 4913, 14174, 31750, 67687, 136608, 269259, 543884};

    const int feat  = lane & 1;           // which 16B feature block this lane fetches
    const int rsrc0 = (lane << 1) & 31;   // route-back: feat0 lane (feat1 = rsrc0|1)

    float o[16];

    #pragma unroll
    for (int t = 0; t < 2; ++t) {
        const int j = (t << 4) + (lane >> 1);   // point served by this lane pair

        const float pxj = __shfl_sync(FULL, px, j);
        const float pyj = __shfl_sync(FULL, py, j);
        const float pzj = __shfl_sync(FULL, pz, j);

        const float cxj = fminf(fmaxf(pxj, 0.0f), 1.0f);
        const float cyj = fminf(fmaxf(pyj, 0.0f), 1.0f);
        const float czj = fminf(fmaxf(pzj, 0.0f), 1.0f);

        #pragma unroll
        for (int l = 0; l < NLV; ++l) {
            const float R = RES[l];

            // multiply-based cell + weights (no fdiv); O(1e-7) off reference,
            // trilinear continuity makes boundary flips benign.
            const float fbx = floorf(cxj * R);
            const float fby = floorf(cyj * R);
            const float fbz = floorf(czj * R);
            const float wx = fmaf(pxj, R, -fbx);
            const float wy = fmaf(pyj, R, -fby);
            const float wz = fmaf(pzj, R, -fbz);

            const int D    = IR[l] + 1;
            const int cell = ((int)fbx * D + (int)fby) * D + (int)fbz;

            // one LDG.128: both feature halves of this cell share a 128B line
            const uint4 u = __ldg(g_cube + ((size_t)OFF[l] + cell) * 2 + feat);

            // half2 pairs: (dz=0, dz=1) for (dx,dy) = 00,01,10,11
            const float2 v00 = __half22float2(*(const __half2*)&u.x);
            const float2 v01 = __half22float2(*(const __half2*)&u.y);
            const float2 v10 = __half22float2(*(const __half2*)&u.z);
            const float2 v11 = __half22float2(*(const __half2*)&u.w);

            const float iwz = 1.0f - wz;
            const float iwy = 1.0f - wy;

            const float z00 = v00.x * iwz + v00.y * wz;   // x=0,y=0
            const float z01 = v01.x * iwz + v01.y * wz;   // x=0,y=1
            const float z10 = v10.x * iwz + v10.y * wz;   // x=1,y=0
            const float z11 = v11.x * iwz + v11.y * wz;   // x=1,y=1

            const float y0 = z00 * iwy + z01 * wy;
            const float y1 = z10 * iwy + z11 * wy;
            const float res = y0 * (1.0f - wx) + y1 * wx;

            // route both features to the owning lane
            const float qa = __shfl_sync(FULL, res, rsrc0);
            const float qb = __shfl_sync(FULL, res, rsrc0 | 1);
            if ((lane >> 4) == t) {
                o[2 * l + 0] = qa * INV_FSCALE;
                o[2 * l + 1] = qb * INV_FSCALE;
            }
        }
    }

    float4* __restrict__ o4 = (float4*)(out + (size_t)i * 16);
    o4[0] = make_float4(o[0],  o[1],  o[2],  o[3]);
    o4[1] = make_float4(o[4],  o[5],  o[6],  o[7]);
    o4[2] = make_float4(o[8],  o[9],  o[10], o[11]);
    o4[3] = make_float4(o[12], o[13], o[14], o[15]);
}

extern "C" void kernel_launch(void* const* d_in, const int* in_sizes, int n_in,
                              void* d_out, int out_size)
{
    const float* x      = (const float*)d_in[0];   // (N_POINTS, 3) f32
    const float* tables = (const float*)d_in[1];   // (16, TABLE_SIZE, 2) f32
    float* out          = (float*)d_out;           // (N_POINTS, 16) f32

    build_cube_fused<<<TOTAL_TILES, 256>>>(tables);
    hash_embed_kernel<<<N_POINTS / 256, 256>>>(x, out);
}